// round 6
// baseline (speedup 1.0000x reference)
#include <cuda_runtime.h>
#include <math.h>

#define NTOK 4096
#define DIM  1024
#define NEXP 8
#define CAP  1280
#define NSLOT (NTOK * 2)
#define ROWW (NEXP * CAP)            // 10240 floats per mask token-row

#define B_LOG   128
#define B_SCAN  1
#define B_ZERO  2048
#define B_BATCH 2560
#define ZERO0   (B_LOG + B_SCAN)             // 129
#define BATCH0  (ZERO0 + B_ZERO)             // 2177
#define NBLK    (BATCH0 + B_BATCH)           // 4737

// Scratch (no device allocs allowed)
__device__ int g_topidx[NSLOT];      // expert id per slot
__device__ int g_pos[NSLOT];         // position within expert, -1 if dropped
__device__ int g_inv[NEXP * CAP];    // (e,pos) -> token, -1 if empty
__device__ int g_done;               // logits blocks completed
__device__ int g_flag;               // scan complete

__global__ void k_init() {
    if (threadIdx.x == 0) { g_done = 0; g_flag = 0; }
}

// ---------------------------------------------------------------------------
// Fused kernel: role by blockIdx.x.
// ---------------------------------------------------------------------------
__global__ __launch_bounds__(256) void k_fused(const float* __restrict__ x,
                                               const float* __restrict__ Wg,
                                               float* __restrict__ gates,
                                               float* __restrict__ mask,
                                               float* __restrict__ batch) {
    const int b = blockIdx.x;

    if (b < B_LOG) {
        // ----- logits: 4 tokens per warp, W in shared -----
        __shared__ float4 sW[NEXP * DIM / 4];        // 32 KB
        const float4* W4 = (const float4*)Wg;
        for (int i = threadIdx.x; i < NEXP * DIM / 4; i += 256) sW[i] = W4[i];
        __syncthreads();

        int warp = threadIdx.x >> 5;
        int lane = threadIdx.x & 31;
        int t0 = (b * 8 + warp) * 4;

        const float4* xr = (const float4*)x + (size_t)t0 * (DIM / 4);
        float acc[4][NEXP];
#pragma unroll
        for (int j = 0; j < 4; j++)
#pragma unroll
            for (int e = 0; e < NEXP; e++) acc[j][e] = 0.f;

#pragma unroll
        for (int i = 0; i < DIM / 128; i++) {
            int o = lane + 32 * i;
            float4 v0 = xr[o];
            float4 v1 = xr[256 + o];
            float4 v2 = xr[512 + o];
            float4 v3 = xr[768 + o];
#pragma unroll
            for (int e = 0; e < NEXP; e++) {
                float4 w = sW[e * 256 + o];
                acc[0][e] += v0.x * w.x + v0.y * w.y + v0.z * w.z + v0.w * w.w;
                acc[1][e] += v1.x * w.x + v1.y * w.y + v1.z * w.z + v1.w * w.w;
                acc[2][e] += v2.x * w.x + v2.y * w.y + v2.z * w.z + v2.w * w.w;
                acc[3][e] += v3.x * w.x + v3.y * w.y + v3.z * w.z + v3.w * w.w;
            }
        }
#pragma unroll
        for (int off = 16; off; off >>= 1)
#pragma unroll
            for (int j = 0; j < 4; j++)
#pragma unroll
                for (int e = 0; e < NEXP; e++)
                    acc[j][e] += __shfl_xor_sync(0xffffffffu, acc[j][e], off);

        if (lane < 4) {
            int t = t0 + lane;
            float v1 = -1e30f, v2 = -1e30f;
            int i1 = 0, i2 = 0;
#pragma unroll
            for (int e = 0; e < NEXP; e++) {
                float a = acc[lane][e];
                if (a > v1)      { v2 = v1; i2 = i1; v1 = a; i1 = e; }
                else if (a > v2) { v2 = a;  i2 = e; }
            }
            float e2 = expf(v2 - v1);
            float inv = 1.f / (1.f + e2);
            gates[2 * t]     = inv;
            gates[2 * t + 1] = e2 * inv;
            g_topidx[2 * t]     = i1;
            g_topidx[2 * t + 1] = i2;
        }
        __syncthreads();
        __threadfence();
        if (threadIdx.x == 0) atomicAdd(&g_done, 1);

    } else if (b == B_LOG) {
        // ----- scan: wait for all logits blocks, then position assignment -----
        if (threadIdx.x == 0) {
            while (atomicAdd(&g_done, 0) < B_LOG) __nanosleep(128);
        }
        __syncthreads();
        __threadfence();

        int tid = threadIdx.x;
        for (int i = tid; i < NEXP * CAP; i += 256) g_inv[i] = -1;

        int base = tid * 32;
        int e_loc[32];
        unsigned short h[NEXP];
#pragma unroll
        for (int e = 0; e < NEXP; e++) h[e] = 0;
#pragma unroll
        for (int j = 0; j < 32; j++) {
            int e = g_topidx[base + j];
            e_loc[j] = e;
            h[e]++;
        }

        __shared__ uint4 ssc[256];
        uint4 v;
        v.x = (unsigned)h[0] | ((unsigned)h[1] << 16);
        v.y = (unsigned)h[2] | ((unsigned)h[3] << 16);
        v.z = (unsigned)h[4] | ((unsigned)h[5] << 16);
        v.w = (unsigned)h[6] | ((unsigned)h[7] << 16);
        ssc[tid] = v;
        __syncthreads();
        for (int off = 1; off < 256; off <<= 1) {
            uint4 a = make_uint4(0, 0, 0, 0);
            if (tid >= off) a = ssc[tid - off];
            __syncthreads();
            v.x += a.x; v.y += a.y; v.z += a.z; v.w += a.w;
            ssc[tid] = v;
            __syncthreads();
        }

        int cnt[NEXP];
        cnt[0] = (int)(v.x & 0xFFFF) - (int)h[0];
        cnt[1] = (int)(v.x >> 16)    - (int)h[1];
        cnt[2] = (int)(v.y & 0xFFFF) - (int)h[2];
        cnt[3] = (int)(v.y >> 16)    - (int)h[3];
        cnt[4] = (int)(v.z & 0xFFFF) - (int)h[4];
        cnt[5] = (int)(v.z >> 16)    - (int)h[5];
        cnt[6] = (int)(v.w & 0xFFFF) - (int)h[6];
        cnt[7] = (int)(v.w >> 16)    - (int)h[7];

#pragma unroll
        for (int j = 0; j < 32; j++) {
            int slot = base + j;
            int e = e_loc[j];
            int p = cnt[e]++;
            if (p < CAP) {
                g_pos[slot] = p;
                g_inv[e * CAP + p] = slot >> 1;
            } else {
                g_pos[slot] = -1;
            }
        }
        __threadfence();
        __syncthreads();
        if (threadIdx.x == 0) atomicExch(&g_flag, 1);

    } else if (b < BATCH0) {
        // ----- zero-fill exp_mask: no dependencies, starts immediately -----
        int zb = b - ZERO0;                       // 0 .. 2047
        float4* dst = (float4*)mask + (size_t)zb * (256 * 20) + threadIdx.x;
        const float4 z = make_float4(0.f, 0.f, 0.f, 0.f);
#pragma unroll
        for (int j = 0; j < 20; j++)
            __stcs(dst + j * 256, z);

    } else {
        // ----- exp_batches rows: wait for scan, then copy/zero 4 rows -----
        if (threadIdx.x == 0) {
            while (atomicAdd(&g_flag, 0) == 0) __nanosleep(128);
        }
        __syncthreads();
        __threadfence();

        int r0 = (b - BATCH0) * 4;
#pragma unroll
        for (int j = 0; j < 4; j++) {
            int r = r0 + j;
            int t = g_inv[r];
            float4 v = make_float4(0.f, 0.f, 0.f, 0.f);
            if (t >= 0)
                v = ((const float4*)x)[(size_t)t * (DIM / 4) + threadIdx.x];
            __stcs((float4*)batch + (size_t)r * (DIM / 4) + threadIdx.x, v);
        }
    }
}

// ---------------------------------------------------------------------------
// Final: scatter <=8192 gate values into the zeroed mask (stream-ordered
// after k_fused, so no race with the zero-fill blocks).
// ---------------------------------------------------------------------------
__global__ __launch_bounds__(256) void k_scatter(const float* __restrict__ gates,
                                                 float* __restrict__ mask) {
    int slot = blockIdx.x * 256 + threadIdx.x;    // 0 .. NSLOT-1
    int p = g_pos[slot];
    if (p >= 0) {
        int e = g_topidx[slot];
        int tok = slot >> 1;
        mask[(size_t)tok * ROWW + e * CAP + p] = gates[slot];
    }
}

// ---------------------------------------------------------------------------
extern "C" void kernel_launch(void* const* d_in, const int* in_sizes, int n_in,
                              void* d_out, int out_size) {
    const float* x  = (const float*)d_in[0];   // [2,2048,1024] f32
    const float* Wg = (const float*)d_in[1];   // [8,1024] f32

    float* out   = (float*)d_out;
    float* gates = out;                                  // 8,192 floats
    float* mask  = out + (size_t)NSLOT;                  // 41,943,040 floats
    float* batch = mask + (size_t)NTOK * ROWW;           // 10,485,760 floats

    k_init<<<1, 32>>>();
    k_fused<<<NBLK, 256>>>(x, Wg, gates, mask, batch);
    k_scatter<<<NSLOT / 256, 256>>>(gates, mask);
}

// round 7
// speedup vs baseline: 1.1717x; 1.1717x over previous
#include <cuda_runtime.h>
#include <math.h>

#define NTOK 4096
#define DIM  1024
#define NEXP 8
#define CAP  1280
#define NSLOT (NTOK * 2)
#define ROWW (NEXP * CAP)            // 10240 floats per mask token-row

#define B_LOG 256                    // logits blocks (2 tokens/warp, 8 warps)

// Scratch (no device allocs allowed)
__device__ int g_topidx[NSLOT];      // expert id per slot
__device__ int g_pos[NSLOT];         // position within expert, -1 if dropped
__device__ int g_inv[NEXP * CAP];    // (e,pos) -> token, -1 if empty
__device__ int g_done;               // logits blocks completed (reset by k_out)

// ---------------------------------------------------------------------------
// Node 1: logits (blocks 0..255) + scan (block 256, spins on g_done).
// ---------------------------------------------------------------------------
__global__ __launch_bounds__(256) void k_route(const float* __restrict__ x,
                                               const float* __restrict__ Wg,
                                               float* __restrict__ gates) {
    const int b = blockIdx.x;

    if (b < B_LOG) {
        // ----- logits: 2 tokens/warp, x fully preloaded to regs (MLP=16) -----
        __shared__ float4 sW[NEXP * DIM / 4];        // 32 KB
        const float4* W4 = (const float4*)Wg;
        for (int i = threadIdx.x; i < NEXP * DIM / 4; i += 256) sW[i] = W4[i];

        int warp = threadIdx.x >> 5;
        int lane = threadIdx.x & 31;
        int t0 = (b * 8 + warp) * 2;

        const float4* xr = (const float4*)x + (size_t)t0 * (DIM / 4);
        float4 xa[8], xb[8];
#pragma unroll
        for (int i = 0; i < 8; i++) xa[i] = xr[lane + 32 * i];
#pragma unroll
        for (int i = 0; i < 8; i++) xb[i] = xr[256 + lane + 32 * i];

        __syncthreads();                             // W ready

        float acc0[NEXP], acc1[NEXP];
#pragma unroll
        for (int e = 0; e < NEXP; e++) { acc0[e] = 0.f; acc1[e] = 0.f; }

#pragma unroll
        for (int i = 0; i < 8; i++) {
            int o = lane + 32 * i;
#pragma unroll
            for (int e = 0; e < NEXP; e++) {
                float4 w = sW[e * 256 + o];
                acc0[e] += xa[i].x * w.x + xa[i].y * w.y + xa[i].z * w.z + xa[i].w * w.w;
                acc1[e] += xb[i].x * w.x + xb[i].y * w.y + xb[i].z * w.z + xb[i].w * w.w;
            }
        }
#pragma unroll
        for (int off = 16; off; off >>= 1)
#pragma unroll
            for (int e = 0; e < NEXP; e++) {
                acc0[e] += __shfl_xor_sync(0xffffffffu, acc0[e], off);
                acc1[e] += __shfl_xor_sync(0xffffffffu, acc1[e], off);
            }

        if (lane < 2) {
            int t = t0 + lane;
            float v1 = -1e30f, v2 = -1e30f;
            int i1 = 0, i2 = 0;
#pragma unroll
            for (int e = 0; e < NEXP; e++) {
                float a = lane ? acc1[e] : acc0[e];
                if (a > v1)      { v2 = v1; i2 = i1; v1 = a; i1 = e; }
                else if (a > v2) { v2 = a;  i2 = e; }
            }
            float e2 = expf(v2 - v1);
            float inv = 1.f / (1.f + e2);
            gates[2 * t]     = inv;
            gates[2 * t + 1] = e2 * inv;
            g_topidx[2 * t]     = i1;
            g_topidx[2 * t + 1] = i2;
        }
        __syncthreads();
        __threadfence();
        if (threadIdx.x == 0) atomicAdd(&g_done, 1);

    } else {
        // ----- scan block: wait for all logits blocks -----
        if (threadIdx.x == 0) {
            while (atomicAdd(&g_done, 0) < B_LOG) __nanosleep(64);
        }
        __syncthreads();
        __threadfence();

        int tid = threadIdx.x;
        for (int i = tid; i < NEXP * CAP; i += 256) g_inv[i] = -1;

        int base = tid * 32;
        int e_loc[32];
        unsigned short h[NEXP];
#pragma unroll
        for (int e = 0; e < NEXP; e++) h[e] = 0;
#pragma unroll
        for (int j = 0; j < 32; j++) {
            int e = g_topidx[base + j];
            e_loc[j] = e;
            h[e]++;
        }

        __shared__ uint4 ssc[256];
        uint4 v;
        v.x = (unsigned)h[0] | ((unsigned)h[1] << 16);
        v.y = (unsigned)h[2] | ((unsigned)h[3] << 16);
        v.z = (unsigned)h[4] | ((unsigned)h[5] << 16);
        v.w = (unsigned)h[6] | ((unsigned)h[7] << 16);
        ssc[tid] = v;
        __syncthreads();
        for (int off = 1; off < 256; off <<= 1) {
            uint4 a = make_uint4(0, 0, 0, 0);
            if (tid >= off) a = ssc[tid - off];
            __syncthreads();
            v.x += a.x; v.y += a.y; v.z += a.z; v.w += a.w;
            ssc[tid] = v;
            __syncthreads();
        }

        int cnt[NEXP];
        cnt[0] = (int)(v.x & 0xFFFF) - (int)h[0];
        cnt[1] = (int)(v.x >> 16)    - (int)h[1];
        cnt[2] = (int)(v.y & 0xFFFF) - (int)h[2];
        cnt[3] = (int)(v.y >> 16)    - (int)h[3];
        cnt[4] = (int)(v.z & 0xFFFF) - (int)h[4];
        cnt[5] = (int)(v.z >> 16)    - (int)h[5];
        cnt[6] = (int)(v.w & 0xFFFF) - (int)h[6];
        cnt[7] = (int)(v.w >> 16)    - (int)h[7];

#pragma unroll
        for (int j = 0; j < 32; j++) {
            int slot = base + j;
            int e = e_loc[j];
            int p = cnt[e]++;
            if (p < CAP) {
                g_pos[slot] = p;
                g_inv[e * CAP + p] = slot >> 1;
            } else {
                g_pos[slot] = -1;
            }
        }
    }
}

// ---------------------------------------------------------------------------
// Node 2: write ALL of exp_batches and exp_mask exactly once, streaming
// stores, gates scattered inline into mask rows. Block 0 resets g_done.
// ---------------------------------------------------------------------------
#define B_BAT (NEXP * CAP / 2)       // 5120 blocks, 2 batch rows each

__global__ __launch_bounds__(256) void k_out(const float* __restrict__ x,
                                             const float* __restrict__ gates,
                                             float* __restrict__ mask,
                                             float* __restrict__ batch) {
    int b = blockIdx.x;
    if (b == 0 && threadIdx.x == 0) g_done = 0;      // reset for next replay

    if (b < B_BAT) {
        // exp_batches: 2 rows per block (1024 floats = 256 x float4 each)
        int r0 = b * 2;
#pragma unroll
        for (int j = 0; j < 2; j++) {
            int r = r0 + j;
            int t = g_inv[r];
            float4 v = make_float4(0.f, 0.f, 0.f, 0.f);
            if (t >= 0)
                v = ((const float4*)x)[(size_t)t * (DIM / 4) + threadIdx.x];
            __stcs((float4*)batch + (size_t)r * (DIM / 4) + threadIdx.x, v);
        }
    } else {
        // exp_mask token-row: 10240 floats, <=2 nonzeros at known offsets
        int tok = b - B_BAT;
        int e0 = g_topidx[2 * tok],  e1 = g_topidx[2 * tok + 1];
        int p0 = g_pos[2 * tok],     p1 = g_pos[2 * tok + 1];
        float g0 = gates[2 * tok],   g1 = gates[2 * tok + 1];
        int off0 = (p0 >= 0) ? e0 * CAP + p0 : -1;
        int off1 = (p1 >= 0) ? e1 * CAP + p1 : -1;
        float4* dst = (float4*)mask + (size_t)tok * (ROWW / 4);
#pragma unroll
        for (int j = 0; j < (ROWW / 4) / 256; j++) { // 10 iterations
            int i4 = j * 256 + threadIdx.x;
            int w = i4 * 4;
            float4 v = make_float4(0.f, 0.f, 0.f, 0.f);
            if (off0 >= w && off0 < w + 4) ((float*)&v)[off0 - w] = g0;
            if (off1 >= w && off1 < w + 4) ((float*)&v)[off1 - w] = g1;
            __stcs(dst + i4, v);
        }
    }
}

// ---------------------------------------------------------------------------
extern "C" void kernel_launch(void* const* d_in, const int* in_sizes, int n_in,
                              void* d_out, int out_size) {
    const float* x  = (const float*)d_in[0];   // [2,2048,1024] f32
    const float* Wg = (const float*)d_in[1];   // [8,1024] f32

    float* out   = (float*)d_out;
    float* gates = out;                                  // 8,192 floats
    float* mask  = out + (size_t)NSLOT;                  // 41,943,040 floats
    float* batch = mask + (size_t)NTOK * ROWW;           // 10,485,760 floats

    k_route<<<B_LOG + 1, 256>>>(x, Wg, gates);
    k_out<<<B_BAT + NTOK, 256>>>(x, gates, mask, batch);
}

// round 8
// speedup vs baseline: 1.2758x; 1.0888x over previous
#include <cuda_runtime.h>
#include <math.h>

#define NTOK 4096
#define DIM  1024
#define NEXP 8
#define CAP  1280
#define NSLOT (NTOK * 2)
#define ROWW (NEXP * CAP)            // 10240 floats per mask token-row

#define B_LOG  256                   // logits blocks (2 tokens/warp, 8 warps)
#define B_ZERO 2048                  // mask zero-fill blocks
#define ZERO0  (B_LOG + 1)           // zero blocks start after logits + scan
#define NBLK1  (ZERO0 + B_ZERO)      // 2305

// Scratch (no device allocs allowed)
__device__ int g_topidx[NSLOT];      // expert id per slot
__device__ int g_pos[NSLOT];         // position within expert, -1 if dropped
__device__ int g_inv[NEXP * CAP];    // (e,pos) -> token, -1 if empty
__device__ int g_done;               // logits blocks completed (reset by k_out)

// ---------------------------------------------------------------------------
// Node 1: logits (blocks 0..255) + scan (block 256, spins on g_done)
//         + mask zero-fill (blocks 257.., independent, no waiting).
// ---------------------------------------------------------------------------
__global__ __launch_bounds__(256) void k_route(const float* __restrict__ x,
                                               const float* __restrict__ Wg,
                                               float* __restrict__ gates,
                                               float* __restrict__ mask) {
    const int b = blockIdx.x;

    if (b >= ZERO0) {
        // ----- mask zero-fill: 81920 B per block, streaming stores -----
        int zb = b - ZERO0;                       // 0 .. 2047
        float4* dst = (float4*)mask + (size_t)zb * (256 * 20) + threadIdx.x;
        const float4 z = make_float4(0.f, 0.f, 0.f, 0.f);
#pragma unroll
        for (int j = 0; j < 20; j++)
            __stcs(dst + j * 256, z);
        return;
    }

    if (b < B_LOG) {
        // ----- logits: 2 tokens/warp, x fully preloaded to regs -----
        __shared__ float4 sW[NEXP * DIM / 4];        // 32 KB
        const float4* W4 = (const float4*)Wg;
        for (int i = threadIdx.x; i < NEXP * DIM / 4; i += 256) sW[i] = W4[i];

        int warp = threadIdx.x >> 5;
        int lane = threadIdx.x & 31;
        int t0 = (b * 8 + warp) * 2;

        const float4* xr = (const float4*)x + (size_t)t0 * (DIM / 4);
        float4 xa[8], xb[8];
#pragma unroll
        for (int i = 0; i < 8; i++) xa[i] = xr[lane + 32 * i];
#pragma unroll
        for (int i = 0; i < 8; i++) xb[i] = xr[256 + lane + 32 * i];

        __syncthreads();                             // W ready

        float acc0[NEXP], acc1[NEXP];
#pragma unroll
        for (int e = 0; e < NEXP; e++) { acc0[e] = 0.f; acc1[e] = 0.f; }

#pragma unroll
        for (int i = 0; i < 8; i++) {
            int o = lane + 32 * i;
#pragma unroll
            for (int e = 0; e < NEXP; e++) {
                float4 w = sW[e * 256 + o];
                acc0[e] += xa[i].x * w.x + xa[i].y * w.y + xa[i].z * w.z + xa[i].w * w.w;
                acc1[e] += xb[i].x * w.x + xb[i].y * w.y + xb[i].z * w.z + xb[i].w * w.w;
            }
        }
#pragma unroll
        for (int off = 16; off; off >>= 1)
#pragma unroll
            for (int e = 0; e < NEXP; e++) {
                acc0[e] += __shfl_xor_sync(0xffffffffu, acc0[e], off);
                acc1[e] += __shfl_xor_sync(0xffffffffu, acc1[e], off);
            }

        if (lane < 2) {
            int t = t0 + lane;
            float v1 = -1e30f, v2 = -1e30f;
            int i1 = 0, i2 = 0;
#pragma unroll
            for (int e = 0; e < NEXP; e++) {
                float a = lane ? acc1[e] : acc0[e];
                if (a > v1)      { v2 = v1; i2 = i1; v1 = a; i1 = e; }
                else if (a > v2) { v2 = a;  i2 = e; }
            }
            float e2 = expf(v2 - v1);
            float inv = 1.f / (1.f + e2);
            gates[2 * t]     = inv;
            gates[2 * t + 1] = e2 * inv;
            g_topidx[2 * t]     = i1;
            g_topidx[2 * t + 1] = i2;
        }
        __syncthreads();
        __threadfence();
        if (threadIdx.x == 0) atomicAdd(&g_done, 1);

    } else {
        // ----- scan block: wait for all logits blocks -----
        if (threadIdx.x == 0) {
            while (atomicAdd(&g_done, 0) < B_LOG) __nanosleep(64);
        }
        __syncthreads();
        __threadfence();

        int tid = threadIdx.x;
        for (int i = tid; i < NEXP * CAP; i += 256) g_inv[i] = -1;

        int base = tid * 32;
        int e_loc[32];
        unsigned short h[NEXP];
#pragma unroll
        for (int e = 0; e < NEXP; e++) h[e] = 0;
#pragma unroll
        for (int j = 0; j < 32; j++) {
            int e = g_topidx[base + j];
            e_loc[j] = e;
            h[e]++;
        }

        __shared__ uint4 ssc[256];
        uint4 v;
        v.x = (unsigned)h[0] | ((unsigned)h[1] << 16);
        v.y = (unsigned)h[2] | ((unsigned)h[3] << 16);
        v.z = (unsigned)h[4] | ((unsigned)h[5] << 16);
        v.w = (unsigned)h[6] | ((unsigned)h[7] << 16);
        ssc[tid] = v;
        __syncthreads();
        for (int off = 1; off < 256; off <<= 1) {
            uint4 a = make_uint4(0, 0, 0, 0);
            if (tid >= off) a = ssc[tid - off];
            __syncthreads();
            v.x += a.x; v.y += a.y; v.z += a.z; v.w += a.w;
            ssc[tid] = v;
            __syncthreads();
        }

        int cnt[NEXP];
        cnt[0] = (int)(v.x & 0xFFFF) - (int)h[0];
        cnt[1] = (int)(v.x >> 16)    - (int)h[1];
        cnt[2] = (int)(v.y & 0xFFFF) - (int)h[2];
        cnt[3] = (int)(v.y >> 16)    - (int)h[3];
        cnt[4] = (int)(v.z & 0xFFFF) - (int)h[4];
        cnt[5] = (int)(v.z >> 16)    - (int)h[5];
        cnt[6] = (int)(v.w & 0xFFFF) - (int)h[6];
        cnt[7] = (int)(v.w >> 16)    - (int)h[7];

#pragma unroll
        for (int j = 0; j < 32; j++) {
            int slot = base + j;
            int e = e_loc[j];
            int p = cnt[e]++;
            if (p < CAP) {
                g_pos[slot] = p;
                g_inv[e * CAP + p] = slot >> 1;
            } else {
                g_pos[slot] = -1;
            }
        }
    }
}

// ---------------------------------------------------------------------------
// Node 2: exp_batches (2 rows/block) + gate scatter into zeroed mask.
// ---------------------------------------------------------------------------
#define B_BAT (NEXP * CAP / 2)       // 5120 blocks, 2 batch rows each
#define NBLK2 (B_BAT + NSLOT / 256)  // + 32 scatter blocks

__global__ __launch_bounds__(256) void k_out(const float* __restrict__ x,
                                             const float* __restrict__ gates,
                                             float* __restrict__ mask,
                                             float* __restrict__ batch) {
    int b = blockIdx.x;
    if (b == 0 && threadIdx.x == 0) g_done = 0;      // reset for next replay

    if (b < B_BAT) {
        // exp_batches: 2 rows per block (1024 floats = 256 x float4 each)
        int r0 = b * 2;
#pragma unroll
        for (int j = 0; j < 2; j++) {
            int r = r0 + j;
            int t = g_inv[r];
            float4 v = make_float4(0.f, 0.f, 0.f, 0.f);
            if (t >= 0)
                v = ((const float4*)x)[(size_t)t * (DIM / 4) + threadIdx.x];
            __stcs((float4*)batch + (size_t)r * (DIM / 4) + threadIdx.x, v);
        }
    } else {
        // scatter gates into the (already zeroed) mask
        int slot = (b - B_BAT) * 256 + threadIdx.x;  // 0 .. NSLOT-1
        int p = g_pos[slot];
        if (p >= 0) {
            int e = g_topidx[slot];
            int tok = slot >> 1;
            mask[(size_t)tok * ROWW + e * CAP + p] = gates[slot];
        }
    }
}

// ---------------------------------------------------------------------------
extern "C" void kernel_launch(void* const* d_in, const int* in_sizes, int n_in,
                              void* d_out, int out_size) {
    const float* x  = (const float*)d_in[0];   // [2,2048,1024] f32
    const float* Wg = (const float*)d_in[1];   // [8,1024] f32

    float* out   = (float*)d_out;
    float* gates = out;                                  // 8,192 floats
    float* mask  = out + (size_t)NSLOT;                  // 41,943,040 floats
    float* batch = mask + (size_t)NTOK * ROWW;           // 10,485,760 floats

    k_route<<<NBLK1, 256>>>(x, Wg, gates, mask);
    k_out<<<NBLK2, 256>>>(x, gates, mask, batch);
}